// round 2
// baseline (speedup 1.0000x reference)
#include <cuda_runtime.h>

#define D 64
#define MAXN 50048

// Scratch (static __device__ — no allocation allowed)
__device__ float g_hw[MAXN * D];   // h @ W, L2-resident (12.8 MB)
__device__ float g_deg[MAXN];      // out-degree accumulator

// ---------------------------------------------------------------------------
// Zero d_out (poisoned) and degree counters. Vectorized float4 stores.
__global__ void zero_kernel(float4* __restrict__ out, int n_f4, int n_nodes) {
    int i = blockIdx.x * blockDim.x + threadIdx.x;
    float4 z = make_float4(0.f, 0.f, 0.f, 0.f);
    if (i < n_f4) out[i] = z;
    if (i < n_nodes) g_deg[i] = 0.f;
}

// ---------------------------------------------------------------------------
// hw = h @ W   (N x 64) @ (64 x 64). One block handles 16 rows.
// W staged in shared (16 KB), h tile in shared (4 KB). Each thread owns one
// output column for 4 rows -> 256 FMA/thread. Bandwidth-trivial (~25 MB).
__global__ __launch_bounds__(256) void gemm_kernel(const float* __restrict__ h,
                                                   const float* __restrict__ W,
                                                   int n) {
    __shared__ float sW[64][64];
    __shared__ float sh[16][64];
    int tid = threadIdx.x;
    int row0 = blockIdx.x * 16;

    // load W: 4096 floats as 1024 float4
    for (int i = tid; i < 1024; i += 256)
        ((float4*)&sW[0][0])[i] = ((const float4*)W)[i];

    // load 16 h rows: 1024 floats as 256 float4, guard tail
    {
        int r = tid >> 4;            // 0..15
        int c4 = tid & 15;           // which float4 in the row
        float4 v = make_float4(0.f, 0.f, 0.f, 0.f);
        if (row0 + r < n)
            v = ((const float4*)(h + (size_t)(row0 + r) * D))[c4];
        ((float4*)&sh[r][0])[c4] = v;
    }
    __syncthreads();

    int col = tid & 63;
    int rg  = tid >> 6;              // 0..3
    #pragma unroll
    for (int rr = 0; rr < 4; rr++) {
        int r = rg * 4 + rr;         // 0..15
        float acc = 0.f;
        #pragma unroll
        for (int k = 0; k < 64; k++)
            acc = fmaf(sh[r][k], sW[k][col], acc);
        int row = row0 + r;
        if (row < n)
            g_hw[(size_t)row * D + col] = acc;
    }
}

// ---------------------------------------------------------------------------
// Out-degree: one RED per edge (ptxas emits RED, no return value needed).
__global__ void deg_kernel(const int* __restrict__ src, int nE) {
    int e = blockIdx.x * blockDim.x + threadIdx.x;
    if (e < nE) atomicAdd(&g_deg[src[e]], 1.0f);
}

// ---------------------------------------------------------------------------
// Scatter-sum of transformed rows: out[dst] += hw[src].
// 16 lanes per edge, each lane does one 16B load (L2-resident hw) + one
// red.global.add.v4.f32 (sm_90+ vector reduction, fire-and-forget).
__global__ __launch_bounds__(256) void scatter_kernel(const int* __restrict__ src,
                                                      const int* __restrict__ dst,
                                                      float* __restrict__ out,
                                                      int nE) {
    long long t = (long long)blockIdx.x * blockDim.x + threadIdx.x;
    int lane = (int)(t & 15);
    long long e = t >> 4;
    if (e >= nE) return;
    int s = src[e];
    int d = dst[e];
    float4 v = ((const float4*)g_hw)[(size_t)s * 16 + lane];
    float* p = out + (size_t)d * D + lane * 4;
    asm volatile("red.global.add.v4.f32 [%0], {%1,%2,%3,%4};\n"
                 :: "l"(p), "f"(v.x), "f"(v.y), "f"(v.z), "f"(v.w)
                 : "memory");
}

// ---------------------------------------------------------------------------
// out = relu(out * rsqrt(deg[row]) + bias[col]), vectorized 4-wide.
__global__ void finalize_kernel(float4* __restrict__ out,
                                const float4* __restrict__ bias4,
                                int n) {
    int i = blockIdx.x * blockDim.x + threadIdx.x;
    if (i >= n * 16) return;
    int row = i >> 4;
    int c4  = i & 15;
    float nm = rsqrtf(g_deg[row]);
    float4 v = out[i];
    float4 b = bias4[c4];
    v.x = fmaxf(fmaf(v.x, nm, b.x), 0.f);
    v.y = fmaxf(fmaf(v.y, nm, b.y), 0.f);
    v.z = fmaxf(fmaf(v.z, nm, b.z), 0.f);
    v.w = fmaxf(fmaf(v.w, nm, b.w), 0.f);
    out[i] = v;
}

// ---------------------------------------------------------------------------
extern "C" void kernel_launch(void* const* d_in, const int* in_sizes, int n_in,
                              void* d_out, int out_size) {
    const float* h    = (const float*)d_in[0];
    const float* W    = (const float*)d_in[1];
    const float* bias = (const float*)d_in[2];
    const int*   src  = (const int*)d_in[3];
    const int*   dst  = (const int*)d_in[4];
    float* out = (float*)d_out;

    int n  = in_sizes[0] / D;     // 50000
    int nE = in_sizes[3];         // 1,650,000

    int n_f4 = n * (D / 4);       // 800000 float4s in out

    zero_kernel<<<(n_f4 + 255) / 256, 256>>>((float4*)out, n_f4, n);
    gemm_kernel<<<(n + 15) / 16, 256>>>(h, W, n);
    deg_kernel<<<(nE + 255) / 256, 256>>>(src, nE);

    long long scatter_threads = (long long)nE * 16;
    int scatter_blocks = (int)((scatter_threads + 255) / 256);
    scatter_kernel<<<scatter_blocks, 256>>>(src, dst, out, nE);

    finalize_kernel<<<(n * 16 + 255) / 256, 256>>>((float4*)out,
                                                   (const float4*)bias, n);
}